// round 11
// baseline (speedup 1.0000x reference)
#include <cuda_runtime.h>
#include <cstdint>

#define B_    8
#define N_    4096
#define FIN_  64
#define S_    1024
#define K_    64
#define H_    64
#define FOUT_ 128
#define BS_   (B_*S_)
#define CH    128              // samples per pipeline chunk
#define NCHUNK (S_/CH)         // 8
#define WBLK  256              // worker blocks per pipe stage
#define TPW   4                // centroids (tiles) per worker block

typedef unsigned long long ull;

// Device-global scratch. All locations written before read within each run
// (and rewritten every run) -> replay-deterministic, no reset needed.
__device__ int g_samp[BS_];
__device__ float g_dist[B_ * N_];
__device__ __align__(16) float g_U[(size_t)B_ * N_ * H_];

// Squared distance with the reference's exact f32 associativity.
__device__ __forceinline__ float sqd(float ax, float ay, float az,
                                     float bx, float by, float bz) {
    float dx = __fadd_rn(ax, -bx);
    float dy = __fadd_rn(ay, -by);
    float dz = __fadd_rn(az, -bz);
    return __fadd_rn(__fadd_rn(__fmul_rn(dx, dx), __fmul_rn(dy, dy)),
                     __fmul_rn(dz, dz));
}

// Packed f32x2 helpers. Per-lane rounding identical to scalar __fadd_rn etc.
__device__ __forceinline__ ull pk2(float lo, float hi) {
    ull r; asm("mov.b64 %0, {%1, %2};" : "=l"(r) : "f"(lo), "f"(hi)); return r;
}
__device__ __forceinline__ ull add2(ull a, ull b) {
    ull r; asm("add.rn.f32x2 %0, %1, %2;" : "=l"(r) : "l"(a), "l"(b)); return r;
}
__device__ __forceinline__ ull mul2(ull a, ull b) {
    ull r; asm("mul.rn.f32x2 %0, %1, %2;" : "=l"(r) : "l"(a), "l"(b)); return r;
}
__device__ __forceinline__ ull fma2(ull a, ull b, ull c) {
    ull r; asm("fma.rn.f32x2 %0, %1, %2, %3;" : "=l"(r) : "l"(a), "l"(b), "l"(c)); return r;
}
__device__ __forceinline__ void upk2(ull p, float& lo, float& hi) {
    asm("mov.b64 {%0, %1}, %2;" : "=f"(lo), "=f"(hi) : "l"(p));
}

// ---------------------------------------------------------------------------
// Kernel A: U'[j][h] = b1[h] + sum_{cf=0..63} x[j][cf] * W1[cf][h]  (proven)
// ---------------------------------------------------------------------------
__global__ __launch_bounds__(256) void u_kernel(
    const float* __restrict__ x, const float* __restrict__ W1,
    const float* __restrict__ b1)
{
    __shared__ __align__(16) float sW[64 * 64];
    __shared__ __align__(16) float sB[64];
    __shared__ __align__(16) float sX[64 * 68];

    const int tid = threadIdx.x;
    const int r0  = blockIdx.x * 64;

    for (int i = tid; i < 64 * 64; i += 256) sW[i] = W1[i];
    if (tid < 64) sB[tid] = b1[tid];
    for (int e = tid; e < 64 * 64; e += 256) {
        int row = e >> 6, cf = e & 63;
        sX[row * 68 + cf] = x[(size_t)(r0 + row) * FIN_ + cf];
    }
    __syncthreads();

    const int n0 = tid >> 2;
    const int hb = (tid & 3) << 4;

    ull acc2[8];
#pragma unroll
    for (int u = 0; u < 8; u++)
        acc2[u] = pk2(sB[hb + 2 * u], sB[hb + 2 * u + 1]);

    const ull* Wp = (const ull*)sW;
    for (int cf = 0; cf < 64; cf++) {
        float m = sX[n0 * 68 + cf];
        ull mm = pk2(m, m);
        const ull* wrow = Wp + cf * 32 + (hb >> 1);
#pragma unroll
        for (int u = 0; u < 8; u++)
            acc2[u] = fma2(mm, wrow[u], acc2[u]);
    }

    float* Urow = g_U + (size_t)(r0 + n0) * H_ + hb;
#pragma unroll
    for (int u = 0; u < 8; u++) {
        float lo, hi;
        upk2(acc2[u], lo, hi);
        float2 o; o.x = lo; o.y = hi;
        *(float2*)(Urow + 2 * u) = o;
    }
}

// ---------------------------------------------------------------------------
// FPS role (R3-proven 256-thread / 16-pt body + chunk entry/exit).
// Processes iterations [s0, s1); dist state persisted in g_dist between
// chunks. s0==0 additionally emits sample 0 and the init distance pass.
// ---------------------------------------------------------------------------
__device__ void fps_role(const float* __restrict__ pos, int b, float* fsm,
                         int s0, int s1)
{
    const int t = threadIdx.x;
    float* sx = fsm;
    float* sy = fsm + N_;
    float* sz = fsm + 2 * N_;
    ull* skey = (ull*)(fsm + 3 * N_);   // 16 entries (8 warps, double buffered)

    const float* P = pos + (size_t)b * N_ * 3;

    for (int e = t; e < N_ * 3; e += 256) {
        float v = P[e];
        int p = e / 3, c = e - p * 3;
        if (c == 0) sx[p] = v; else if (c == 1) sy[p] = v; else sz[p] = v;
    }
    __syncthreads();

    const int base = t * 16;
    ull px[8], py[8], pz[8];
#pragma unroll
    for (int i = 0; i < 8; i++) {
        px[i] = pk2(sx[base + 2 * i], sx[base + 2 * i + 1]);
        py[i] = pk2(sy[base + 2 * i], sy[base + 2 * i + 1]);
        pz[i] = pk2(sz[base + 2 * i], sz[base + 2 * i + 1]);
    }

    float dist[16];
    int itstart;
    if (s0 == 0) {
        ull nqx = pk2(-sx[0], -sx[0]);
        ull nqy = pk2(-sy[0], -sy[0]);
        ull nqz = pk2(-sz[0], -sz[0]);
#pragma unroll
        for (int i = 0; i < 8; i++) {
            ull dx = add2(px[i], nqx);
            ull dy = add2(py[i], nqy);
            ull dz = add2(pz[i], nqz);
            ull s = add2(add2(mul2(dx, dx), mul2(dy, dy)), mul2(dz, dz));
            upk2(s, dist[2 * i], dist[2 * i + 1]);
        }
        if (t == 0) g_samp[b * S_] = 0;
        itstart = 1;
    } else {
#pragma unroll
        for (int i = 0; i < 16; i++) dist[i] = g_dist[b * N_ + base + i];
        itstart = s0;
    }

    const int lane = t & 31;
    const int wid  = t >> 5;

    for (int it = itstart; it < s1; it++) {
        // per-thread max tree (value only)
        float m0 = fmaxf(dist[0], dist[1]),   m1 = fmaxf(dist[2], dist[3]);
        float m2 = fmaxf(dist[4], dist[5]),   m3 = fmaxf(dist[6], dist[7]);
        float m4 = fmaxf(dist[8], dist[9]),   m5 = fmaxf(dist[10], dist[11]);
        float m6 = fmaxf(dist[12], dist[13]), m7 = fmaxf(dist[14], dist[15]);
        m0 = fmaxf(m0, m1); m2 = fmaxf(m2, m3); m4 = fmaxf(m4, m5); m6 = fmaxf(m6, m7);
        m0 = fmaxf(m0, m2); m4 = fmaxf(m4, m6);
        const float lm = fmaxf(m0, m4);

        const float wm = __uint_as_float(
            __reduce_max_sync(0xFFFFFFFFu, __float_as_uint(lm)));

        unsigned ball = __ballot_sync(0xFFFFFFFFu, lm == wm);
        int src = __ffs(ball) - 1;
        int li = 0;
#pragma unroll
        for (int i = 15; i >= 0; i--) if (dist[i] == wm) li = i;
        int gidx = __shfl_sync(0xFFFFFFFFu, base + li, src);

        const int buf = (it & 1) << 3;
        if (lane == 0)
            skey[buf + wid] = (((ull)__float_as_uint(wm)) << 32)
                              | (unsigned)(0xFFFFFFFFu - (unsigned)gidx);
        __syncthreads();

        ull k0 = skey[buf + 0], k1 = skey[buf + 1];
        ull k2 = skey[buf + 2], k3 = skey[buf + 3];
        ull k4 = skey[buf + 4], k5 = skey[buf + 5];
        ull k6 = skey[buf + 6], k7 = skey[buf + 7];
        k0 = (k1 > k0) ? k1 : k0;  k2 = (k3 > k2) ? k3 : k2;
        k4 = (k5 > k4) ? k5 : k4;  k6 = (k7 > k6) ? k7 : k6;
        k0 = (k2 > k0) ? k2 : k0;  k4 = (k6 > k4) ? k6 : k4;
        k0 = (k4 > k0) ? k4 : k0;
        const int widx =
            ((int)(0xFFFFFFFFu - (unsigned)(k0 & 0xFFFFFFFFull))) & (N_ - 1);

        if (t == 0) g_samp[b * S_ + it] = widx;

        const float qx = sx[widx], qy = sy[widx], qz = sz[widx];
        ull nqx = pk2(-qx, -qx);
        ull nqy = pk2(-qy, -qy);
        ull nqz = pk2(-qz, -qz);
#pragma unroll
        for (int i = 0; i < 8; i++) {
            ull dx = add2(px[i], nqx);
            ull dy = add2(py[i], nqy);
            ull dz = add2(pz[i], nqz);
            ull s = add2(add2(mul2(dx, dx), mul2(dy, dy)), mul2(dz, dz));
            float lo, hi;
            upk2(s, lo, hi);
            dist[2 * i]     = fminf(dist[2 * i], lo);
            dist[2 * i + 1] = fminf(dist[2 * i + 1], hi);
        }
    }

#pragma unroll
    for (int i = 0; i < 16; i++) g_dist[b * N_ + base + i] = dist[i];
}

// ---------------------------------------------------------------------------
// Worker role: radius (R9 warp code, lists in SMEM) + MLP (R9 exact code)
// for TPW centroids of chunk [ws0, ws0+CH). Reads only state written by
// PREVIOUS kernels (g_samp, g_U) -> no intra-kernel communication.
// Worker SMEM layout (floats): sW1b 192 | sH 4352 | sPart 256 | snbr 256(int)
//                              | scnt 4(int) | scx 4 | scy 4 | scz 4
// ---------------------------------------------------------------------------
__device__ void worker_role(const float* __restrict__ pos,
                            const float* __restrict__ W1,
                            const float* __restrict__ W2,
                            const float* __restrict__ b2,
                            float* __restrict__ out, int write_tail,
                            int ws0, float* sm_)
{
    float* sW1b = sm_;                  // 192
    float* sH   = sm_ + 192;            // 4352 (row pitch 68)
    float* sPart= sm_ + 192 + 4352;     // 256
    int*   snbr = (int*)(sPart + 256);  // TPW*64
    int*   scnt = snbr + TPW * K_;      // TPW
    float* scx  = (float*)(scnt + TPW);
    float* scy  = scx + TPW;
    float* scz  = scy + TPW;

    const int tid = threadIdx.x;
    for (int i = tid; i < 192; i += 256) sW1b[i] = W1[64 * 64 + i];

    const int f = tid & 127;
    ull w2p[32];
#pragma unroll
    for (int u = 0; u < 32; u++)
        w2p[u] = pk2(W2[(2 * u) * FOUT_ + f], W2[(2 * u + 1) * FOUT_ + f]);
    const float b2r = b2[f];

    const int lane = tid & 31;
    const int w    = tid >> 5;
    const int bw   = blockIdx.x - B_;
    const float r2 = (float)(0.2 * 0.2);

    // ---- radius: warps 0..TPW-1, one centroid each (R9-proven body) ----
    if (w < TPW) {
        const int ci_idx = bw * TPW + w;
        const int b    = ci_idx >> 7;              // 128 sidx per cloud per chunk
        const int sidx = ws0 + (ci_idx & 127);
        const int g    = b * S_ + sidx;
        const int ci   = g_samp[g];
        const float* P = pos + (size_t)b * N_ * 3;
        const float cx = P[ci * 3 + 0];
        const float cy = P[ci * 3 + 1];
        const float cz = P[ci * 3 + 2];

        int cnt = 0;
        for (int j0 = 0; j0 < N_ && cnt < K_; j0 += 32) {
            int j = j0 + lane;
            float d2 = sqd(cx, cy, cz, P[j*3+0], P[j*3+1], P[j*3+2]);
            bool iw = (d2 <= r2);
            unsigned m = __ballot_sync(0xFFFFFFFFu, iw);
            int rank = __popc(m & ((1u << lane) - 1u));
            if (iw && (cnt + rank) < K_) snbr[w * K_ + cnt + rank] = j;
            cnt += __popc(m);
        }
        if (lane == 0) {
            scnt[w] = (cnt < K_) ? cnt : K_;
            scx[w] = cx; scy[w] = cy; scz[w] = cz;
        }
    }
    __syncthreads();

    const int n0 = tid >> 2;
    const int hb = (tid & 3) << 4;

    float* tail_pos = out + (size_t)BS_ * FOUT_;
    float* tail_bat = out + (size_t)BS_ * FOUT_ + (size_t)BS_ * 3;

    for (int ii = 0; ii < TPW; ii++) {
        const int ci_idx = bw * TPW + ii;
        const int b    = ci_idx >> 7;
        const int sidx = ws0 + (ci_idx & 127);
        const int g    = b * S_ + sidx;
        const int c    = scnt[ii];
        const float cx = scx[ii], cy = scy[ii], cz = scz[ii];
        const float* P = pos + (size_t)b * N_ * 3;

        // ---- phase 1 (R9 exact) ----
        {
            const int jn = snbr[ii * K_ + ((n0 < c) ? n0 : 0)];
            const float dpx = __fadd_rn(P[jn * 3 + 0], -cx);
            const float dpy = __fadd_rn(P[jn * 3 + 1], -cy);
            const float dpz = __fadd_rn(P[jn * 3 + 2], -cz);

            const ulonglong2* Up =
                (const ulonglong2*)(g_U + (size_t)(b * N_ + jn) * H_ + hb);
            ull acc2[8];
#pragma unroll
            for (int u = 0; u < 4; u++) {
                ulonglong2 v = Up[u];
                acc2[2 * u]     = v.x;
                acc2[2 * u + 1] = v.y;
            }
            const ull mx = pk2(dpx, dpx);
            const ull my = pk2(dpy, dpy);
            const ull mz = pk2(dpz, dpz);
            const ull* wx = (const ull*)(sW1b)       + (hb >> 1);
            const ull* wy = (const ull*)(sW1b + 64)  + (hb >> 1);
            const ull* wz = (const ull*)(sW1b + 128) + (hb >> 1);
#pragma unroll
            for (int u = 0; u < 8; u++) acc2[u] = fma2(mx, wx[u], acc2[u]);
#pragma unroll
            for (int u = 0; u < 8; u++) acc2[u] = fma2(my, wy[u], acc2[u]);
#pragma unroll
            for (int u = 0; u < 8; u++) acc2[u] = fma2(mz, wz[u], acc2[u]);
#pragma unroll
            for (int u = 0; u < 8; u++) {
                float lo, hi;
                upk2(acc2[u], lo, hi);
                float2 o;
                o.x = fmaxf(lo, 0.f);
                o.y = fmaxf(hi, 0.f);
                *(float2*)&sH[n0 * 68 + hb + 2 * u] = o;
            }
        }
        __syncthreads();

        // ---- phase 2 (R9 exact) ----
        {
            const int kh = tid >> 7;
            float best = __int_as_float(0xff800000);
            for (int k = kh; k < c; k += 2) {
                const ulonglong2* hv = (const ulonglong2*)(sH + k * 68);
                ull aA = pk2(0.f, 0.f), aB = pk2(0.f, 0.f);
#pragma unroll
                for (int q = 0; q < 16; q++) {
                    ulonglong2 hh = hv[q];
                    aA = fma2(hh.x, w2p[2 * q],     aA);
                    aB = fma2(hh.y, w2p[2 * q + 1], aB);
                }
                ull s2 = add2(aA, aB);
                float lo, hi;
                upk2(s2, lo, hi);
                best = fmaxf(best, __fadd_rn(lo, hi));
            }
            sPart[tid] = best;
            __syncthreads();
            if (tid < 128) {
                float m = fmaxf(sPart[tid], sPart[tid + 128]);
                out[(size_t)g * FOUT_ + f] = (c > 0) ? __fadd_rn(m, b2r) : 0.0f;
            }
            if (write_tail && tid >= 252) {
                int c3 = tid - 252;
                if      (c3 == 0) tail_pos[g * 3 + 0] = cx;
                else if (c3 == 1) tail_pos[g * 3 + 1] = cy;
                else if (c3 == 2) tail_pos[g * 3 + 2] = cz;
                else              tail_bat[g] = (float)b;
            }
        }
        __syncthreads();
    }
}

// ---------------------------------------------------------------------------
// Pipe kernel: blocks 0..7 run FPS chunk [fs0, fs1); blocks 8.. run
// radius+MLP for chunk [ws0, ws0+CH). All producer->consumer edges cross
// kernel boundaries; there is NO intra-kernel communication.
// ---------------------------------------------------------------------------
#define SMEM_BYTES ((3 * N_ + 32) * 4)   // 49280 (fps role; worker uses less)

__global__ __launch_bounds__(256) void pipe_kernel(
    const float* __restrict__ pos, const float* __restrict__ W1,
    const float* __restrict__ W2, const float* __restrict__ b2,
    float* __restrict__ out, int write_tail, int fs0, int fs1, int ws0)
{
    extern __shared__ __align__(16) float sm[];
    const int bid = blockIdx.x;
    if (bid < B_) {
        if (fs0 < S_) fps_role(pos, bid, sm, fs0, fs1);
        return;
    }
    if (ws0 >= 0)
        worker_role(pos, W1, W2, b2, out, write_tail, ws0, sm);
}

// ---------------------------------------------------------------------------
extern "C" void kernel_launch(void* const* d_in, const int* in_sizes, int n_in,
                              void* d_out, int out_size) {
    const float *x = nullptr, *pos = nullptr, *W1 = nullptr, *b1 = nullptr,
                *W2 = nullptr, *b2 = nullptr;
    for (int i = 0; i < n_in; i++) {
        switch (in_sizes[i]) {
            case B_ * N_ * FIN_:  x   = (const float*)d_in[i]; break;
            case B_ * N_ * 3:     pos = (const float*)d_in[i]; break;
            case (FIN_ + 3) * H_: W1  = (const float*)d_in[i]; break;
            case H_:              b1  = (const float*)d_in[i]; break;
            case H_ * FOUT_:      W2  = (const float*)d_in[i]; break;
            case FOUT_:           b2  = (const float*)d_in[i]; break;
            default: break; // batch ids reconstructed analytically
        }
    }
    float* out = (float*)d_out;

    const int total3 = BS_ * FOUT_ + BS_ * 3 + BS_;
    const int tail = (out_size >= total3) ? 1 : 0;

    u_kernel<<<(B_ * N_) / 64, 256>>>(x, W1, b1);

    cudaFuncSetAttribute(pipe_kernel,
                         cudaFuncAttributeMaxDynamicSharedMemorySize, SMEM_BYTES);

    for (int p = 0; p <= NCHUNK; p++) {
        const int fs0 = p * CH;
        const int fs1 = fs0 + CH;
        const int ws0 = (p - 1) * CH;
        const int grid = (p == 0) ? B_ : (B_ + WBLK);
        pipe_kernel<<<grid, 256, SMEM_BYTES>>>(pos, W1, W2, b2, out, tail,
                                               fs0, fs1, ws0);
    }
}

// round 12
// speedup vs baseline: 1.0028x; 1.0028x over previous
#include <cuda_runtime.h>
#include <cstdint>

#define B_    8
#define N_    4096
#define FIN_  64
#define S_    1024
#define K_    64
#define H_    64
#define FOUT_ 128
#define BS_   (B_*S_)
#define CH    128              // samples per pipeline chunk
#define NCHUNK (S_/CH)         // 8
#define WBLK  256              // worker blocks per pipe stage
#define TPW   4                // centroids (tiles) per worker block

typedef unsigned long long ull;

// Device-global scratch. All locations written before read within each run
// (and rewritten every run) -> replay-deterministic, no reset needed.
__device__ int g_samp[BS_];
__device__ float g_dist[B_ * N_];
__device__ __align__(16) float g_U[(size_t)B_ * N_ * H_];

// Squared distance with the reference's exact f32 associativity.
__device__ __forceinline__ float sqd(float ax, float ay, float az,
                                     float bx, float by, float bz) {
    float dx = __fadd_rn(ax, -bx);
    float dy = __fadd_rn(ay, -by);
    float dz = __fadd_rn(az, -bz);
    return __fadd_rn(__fadd_rn(__fmul_rn(dx, dx), __fmul_rn(dy, dy)),
                     __fmul_rn(dz, dz));
}

// Packed f32x2 helpers. Per-lane rounding identical to scalar __fadd_rn etc.
__device__ __forceinline__ ull pk2(float lo, float hi) {
    ull r; asm("mov.b64 %0, {%1, %2};" : "=l"(r) : "f"(lo), "f"(hi)); return r;
}
__device__ __forceinline__ ull add2(ull a, ull b) {
    ull r; asm("add.rn.f32x2 %0, %1, %2;" : "=l"(r) : "l"(a), "l"(b)); return r;
}
__device__ __forceinline__ ull mul2(ull a, ull b) {
    ull r; asm("mul.rn.f32x2 %0, %1, %2;" : "=l"(r) : "l"(a), "l"(b)); return r;
}
__device__ __forceinline__ ull fma2(ull a, ull b, ull c) {
    ull r; asm("fma.rn.f32x2 %0, %1, %2, %3;" : "=l"(r) : "l"(a), "l"(b), "l"(c)); return r;
}
__device__ __forceinline__ void upk2(ull p, float& lo, float& hi) {
    asm("mov.b64 {%0, %1}, %2;" : "=f"(lo), "=f"(hi) : "l"(p));
}

// ---------------------------------------------------------------------------
// Kernel A: U'[j][h] = b1[h] + sum_{cf=0..63} x[j][cf] * W1[cf][h]  (proven)
// ---------------------------------------------------------------------------
__global__ __launch_bounds__(256) void u_kernel(
    const float* __restrict__ x, const float* __restrict__ W1,
    const float* __restrict__ b1)
{
    __shared__ __align__(16) float sW[64 * 64];
    __shared__ __align__(16) float sB[64];
    __shared__ __align__(16) float sX[64 * 68];

    const int tid = threadIdx.x;
    const int r0  = blockIdx.x * 64;

    for (int i = tid; i < 64 * 64; i += 256) sW[i] = W1[i];
    if (tid < 64) sB[tid] = b1[tid];
    for (int e = tid; e < 64 * 64; e += 256) {
        int row = e >> 6, cf = e & 63;
        sX[row * 68 + cf] = x[(size_t)(r0 + row) * FIN_ + cf];
    }
    __syncthreads();

    const int n0 = tid >> 2;
    const int hb = (tid & 3) << 4;

    ull acc2[8];
#pragma unroll
    for (int u = 0; u < 8; u++)
        acc2[u] = pk2(sB[hb + 2 * u], sB[hb + 2 * u + 1]);

    const ull* Wp = (const ull*)sW;
    for (int cf = 0; cf < 64; cf++) {
        float m = sX[n0 * 68 + cf];
        ull mm = pk2(m, m);
        const ull* wrow = Wp + cf * 32 + (hb >> 1);
#pragma unroll
        for (int u = 0; u < 8; u++)
            acc2[u] = fma2(mm, wrow[u], acc2[u]);
    }

    float* Urow = g_U + (size_t)(r0 + n0) * H_ + hb;
#pragma unroll
    for (int u = 0; u < 8; u++) {
        float lo, hi;
        upk2(acc2[u], lo, hi);
        float2 o; o.x = lo; o.y = hi;
        *(float2*)(Urow + 2 * u) = o;
    }
}

// ---------------------------------------------------------------------------
// FPS role (R3-proven 256-thread / 16-pt body + chunk entry/exit).
// Processes iterations [s0, s1); dist state persisted in g_dist between
// chunks. s0==0 additionally emits sample 0 and the init distance pass.
// ---------------------------------------------------------------------------
__device__ void fps_role(const float* __restrict__ pos, int b, float* fsm,
                         int s0, int s1)
{
    const int t = threadIdx.x;
    float* sx = fsm;
    float* sy = fsm + N_;
    float* sz = fsm + 2 * N_;
    ull* skey = (ull*)(fsm + 3 * N_);   // 16 entries (8 warps, double buffered)

    const float* P = pos + (size_t)b * N_ * 3;

    for (int e = t; e < N_ * 3; e += 256) {
        float v = P[e];
        int p = e / 3, c = e - p * 3;
        if (c == 0) sx[p] = v; else if (c == 1) sy[p] = v; else sz[p] = v;
    }
    __syncthreads();

    const int base = t * 16;
    ull px[8], py[8], pz[8];
#pragma unroll
    for (int i = 0; i < 8; i++) {
        px[i] = pk2(sx[base + 2 * i], sx[base + 2 * i + 1]);
        py[i] = pk2(sy[base + 2 * i], sy[base + 2 * i + 1]);
        pz[i] = pk2(sz[base + 2 * i], sz[base + 2 * i + 1]);
    }

    float dist[16];
    int itstart;
    if (s0 == 0) {
        ull nqx = pk2(-sx[0], -sx[0]);
        ull nqy = pk2(-sy[0], -sy[0]);
        ull nqz = pk2(-sz[0], -sz[0]);
#pragma unroll
        for (int i = 0; i < 8; i++) {
            ull dx = add2(px[i], nqx);
            ull dy = add2(py[i], nqy);
            ull dz = add2(pz[i], nqz);
            ull s = add2(add2(mul2(dx, dx), mul2(dy, dy)), mul2(dz, dz));
            upk2(s, dist[2 * i], dist[2 * i + 1]);
        }
        if (t == 0) g_samp[b * S_] = 0;
        itstart = 1;
    } else {
#pragma unroll
        for (int i = 0; i < 16; i++) dist[i] = g_dist[b * N_ + base + i];
        itstart = s0;
    }

    const int lane = t & 31;
    const int wid  = t >> 5;

    for (int it = itstart; it < s1; it++) {
        // per-thread max tree (value only)
        float m0 = fmaxf(dist[0], dist[1]),   m1 = fmaxf(dist[2], dist[3]);
        float m2 = fmaxf(dist[4], dist[5]),   m3 = fmaxf(dist[6], dist[7]);
        float m4 = fmaxf(dist[8], dist[9]),   m5 = fmaxf(dist[10], dist[11]);
        float m6 = fmaxf(dist[12], dist[13]), m7 = fmaxf(dist[14], dist[15]);
        m0 = fmaxf(m0, m1); m2 = fmaxf(m2, m3); m4 = fmaxf(m4, m5); m6 = fmaxf(m6, m7);
        m0 = fmaxf(m0, m2); m4 = fmaxf(m4, m6);
        const float lm = fmaxf(m0, m4);

        const float wm = __uint_as_float(
            __reduce_max_sync(0xFFFFFFFFu, __float_as_uint(lm)));

        unsigned ball = __ballot_sync(0xFFFFFFFFu, lm == wm);
        int src = __ffs(ball) - 1;
        int li = 0;
#pragma unroll
        for (int i = 15; i >= 0; i--) if (dist[i] == wm) li = i;
        int gidx = __shfl_sync(0xFFFFFFFFu, base + li, src);

        const int buf = (it & 1) << 3;
        if (lane == 0)
            skey[buf + wid] = (((ull)__float_as_uint(wm)) << 32)
                              | (unsigned)(0xFFFFFFFFu - (unsigned)gidx);
        __syncthreads();

        ull k0 = skey[buf + 0], k1 = skey[buf + 1];
        ull k2 = skey[buf + 2], k3 = skey[buf + 3];
        ull k4 = skey[buf + 4], k5 = skey[buf + 5];
        ull k6 = skey[buf + 6], k7 = skey[buf + 7];
        k0 = (k1 > k0) ? k1 : k0;  k2 = (k3 > k2) ? k3 : k2;
        k4 = (k5 > k4) ? k5 : k4;  k6 = (k7 > k6) ? k7 : k6;
        k0 = (k2 > k0) ? k2 : k0;  k4 = (k6 > k4) ? k6 : k4;
        k0 = (k4 > k0) ? k4 : k0;
        const int widx =
            ((int)(0xFFFFFFFFu - (unsigned)(k0 & 0xFFFFFFFFull))) & (N_ - 1);

        if (t == 0) g_samp[b * S_ + it] = widx;

        const float qx = sx[widx], qy = sy[widx], qz = sz[widx];
        ull nqx = pk2(-qx, -qx);
        ull nqy = pk2(-qy, -qy);
        ull nqz = pk2(-qz, -qz);
#pragma unroll
        for (int i = 0; i < 8; i++) {
            ull dx = add2(px[i], nqx);
            ull dy = add2(py[i], nqy);
            ull dz = add2(pz[i], nqz);
            ull s = add2(add2(mul2(dx, dx), mul2(dy, dy)), mul2(dz, dz));
            float lo, hi;
            upk2(s, lo, hi);
            dist[2 * i]     = fminf(dist[2 * i], lo);
            dist[2 * i + 1] = fminf(dist[2 * i + 1], hi);
        }
    }

#pragma unroll
    for (int i = 0; i < 16; i++) g_dist[b * N_ + base + i] = dist[i];
}

// ---------------------------------------------------------------------------
// Worker role: radius (R9 warp code, lists in SMEM) + MLP (R9 exact code)
// for TPW centroids of chunk [ws0, ws0+CH). Reads only state written by
// PREVIOUS kernels (g_samp, g_U) -> no intra-kernel communication.
// Worker SMEM layout (floats): sW1b 192 | sH 4352 | sPart 256 | snbr 256(int)
//                              | scnt 4(int) | scx 4 | scy 4 | scz 4
// ---------------------------------------------------------------------------
__device__ void worker_role(const float* __restrict__ pos,
                            const float* __restrict__ W1,
                            const float* __restrict__ W2,
                            const float* __restrict__ b2,
                            float* __restrict__ out, int write_tail,
                            int ws0, float* sm_)
{
    float* sW1b = sm_;                  // 192
    float* sH   = sm_ + 192;            // 4352 (row pitch 68)
    float* sPart= sm_ + 192 + 4352;     // 256
    int*   snbr = (int*)(sPart + 256);  // TPW*64
    int*   scnt = snbr + TPW * K_;      // TPW
    float* scx  = (float*)(scnt + TPW);
    float* scy  = scx + TPW;
    float* scz  = scy + TPW;

    const int tid = threadIdx.x;
    for (int i = tid; i < 192; i += 256) sW1b[i] = W1[64 * 64 + i];

    const int f = tid & 127;
    ull w2p[32];
#pragma unroll
    for (int u = 0; u < 32; u++)
        w2p[u] = pk2(W2[(2 * u) * FOUT_ + f], W2[(2 * u + 1) * FOUT_ + f]);
    const float b2r = b2[f];

    const int lane = tid & 31;
    const int w    = tid >> 5;
    const int bw   = blockIdx.x - B_;
    const float r2 = (float)(0.2 * 0.2);

    // ---- radius: warps 0..TPW-1, one centroid each (R9-proven body) ----
    if (w < TPW) {
        const int ci_idx = bw * TPW + w;
        const int b    = ci_idx >> 7;              // 128 sidx per cloud per chunk
        const int sidx = ws0 + (ci_idx & 127);
        const int g    = b * S_ + sidx;
        const int ci   = g_samp[g];
        const float* P = pos + (size_t)b * N_ * 3;
        const float cx = P[ci * 3 + 0];
        const float cy = P[ci * 3 + 1];
        const float cz = P[ci * 3 + 2];

        int cnt = 0;
        for (int j0 = 0; j0 < N_ && cnt < K_; j0 += 32) {
            int j = j0 + lane;
            float d2 = sqd(cx, cy, cz, P[j*3+0], P[j*3+1], P[j*3+2]);
            bool iw = (d2 <= r2);
            unsigned m = __ballot_sync(0xFFFFFFFFu, iw);
            int rank = __popc(m & ((1u << lane) - 1u));
            if (iw && (cnt + rank) < K_) snbr[w * K_ + cnt + rank] = j;
            cnt += __popc(m);
        }
        if (lane == 0) {
            scnt[w] = (cnt < K_) ? cnt : K_;
            scx[w] = cx; scy[w] = cy; scz[w] = cz;
        }
    }
    __syncthreads();

    const int n0 = tid >> 2;
    const int hb = (tid & 3) << 4;

    float* tail_pos = out + (size_t)BS_ * FOUT_;
    float* tail_bat = out + (size_t)BS_ * FOUT_ + (size_t)BS_ * 3;

    for (int ii = 0; ii < TPW; ii++) {
        const int ci_idx = bw * TPW + ii;
        const int b    = ci_idx >> 7;
        const int sidx = ws0 + (ci_idx & 127);
        const int g    = b * S_ + sidx;
        const int c    = scnt[ii];
        const float cx = scx[ii], cy = scy[ii], cz = scz[ii];
        const float* P = pos + (size_t)b * N_ * 3;

        // ---- phase 1 (R9 exact) ----
        {
            const int jn = snbr[ii * K_ + ((n0 < c) ? n0 : 0)];
            const float dpx = __fadd_rn(P[jn * 3 + 0], -cx);
            const float dpy = __fadd_rn(P[jn * 3 + 1], -cy);
            const float dpz = __fadd_rn(P[jn * 3 + 2], -cz);

            const ulonglong2* Up =
                (const ulonglong2*)(g_U + (size_t)(b * N_ + jn) * H_ + hb);
            ull acc2[8];
#pragma unroll
            for (int u = 0; u < 4; u++) {
                ulonglong2 v = Up[u];
                acc2[2 * u]     = v.x;
                acc2[2 * u + 1] = v.y;
            }
            const ull mx = pk2(dpx, dpx);
            const ull my = pk2(dpy, dpy);
            const ull mz = pk2(dpz, dpz);
            const ull* wx = (const ull*)(sW1b)       + (hb >> 1);
            const ull* wy = (const ull*)(sW1b + 64)  + (hb >> 1);
            const ull* wz = (const ull*)(sW1b + 128) + (hb >> 1);
#pragma unroll
            for (int u = 0; u < 8; u++) acc2[u] = fma2(mx, wx[u], acc2[u]);
#pragma unroll
            for (int u = 0; u < 8; u++) acc2[u] = fma2(my, wy[u], acc2[u]);
#pragma unroll
            for (int u = 0; u < 8; u++) acc2[u] = fma2(mz, wz[u], acc2[u]);
#pragma unroll
            for (int u = 0; u < 8; u++) {
                float lo, hi;
                upk2(acc2[u], lo, hi);
                float2 o;
                o.x = fmaxf(lo, 0.f);
                o.y = fmaxf(hi, 0.f);
                *(float2*)&sH[n0 * 68 + hb + 2 * u] = o;
            }
        }
        __syncthreads();

        // ---- phase 2 (R9 exact) ----
        {
            const int kh = tid >> 7;
            float best = __int_as_float(0xff800000);
            for (int k = kh; k < c; k += 2) {
                const ulonglong2* hv = (const ulonglong2*)(sH + k * 68);
                ull aA = pk2(0.f, 0.f), aB = pk2(0.f, 0.f);
#pragma unroll
                for (int q = 0; q < 16; q++) {
                    ulonglong2 hh = hv[q];
                    aA = fma2(hh.x, w2p[2 * q],     aA);
                    aB = fma2(hh.y, w2p[2 * q + 1], aB);
                }
                ull s2 = add2(aA, aB);
                float lo, hi;
                upk2(s2, lo, hi);
                best = fmaxf(best, __fadd_rn(lo, hi));
            }
            sPart[tid] = best;
            __syncthreads();
            if (tid < 128) {
                float m = fmaxf(sPart[tid], sPart[tid + 128]);
                out[(size_t)g * FOUT_ + f] = (c > 0) ? __fadd_rn(m, b2r) : 0.0f;
            }
            if (write_tail && tid >= 252) {
                int c3 = tid - 252;
                if      (c3 == 0) tail_pos[g * 3 + 0] = cx;
                else if (c3 == 1) tail_pos[g * 3 + 1] = cy;
                else if (c3 == 2) tail_pos[g * 3 + 2] = cz;
                else              tail_bat[g] = (float)b;
            }
        }
        __syncthreads();
    }
}

// ---------------------------------------------------------------------------
// Pipe kernel: blocks 0..7 run FPS chunk [fs0, fs1); blocks 8.. run
// radius+MLP for chunk [ws0, ws0+CH). All producer->consumer edges cross
// kernel boundaries; there is NO intra-kernel communication.
// ---------------------------------------------------------------------------
#define SMEM_BYTES ((3 * N_ + 32) * 4)   // 49280 (fps role; worker uses less)

__global__ __launch_bounds__(256) void pipe_kernel(
    const float* __restrict__ pos, const float* __restrict__ W1,
    const float* __restrict__ W2, const float* __restrict__ b2,
    float* __restrict__ out, int write_tail, int fs0, int fs1, int ws0)
{
    extern __shared__ __align__(16) float sm[];
    const int bid = blockIdx.x;
    if (bid < B_) {
        if (fs0 < S_) fps_role(pos, bid, sm, fs0, fs1);
        return;
    }
    if (ws0 >= 0)
        worker_role(pos, W1, W2, b2, out, write_tail, ws0, sm);
}

// ---------------------------------------------------------------------------
extern "C" void kernel_launch(void* const* d_in, const int* in_sizes, int n_in,
                              void* d_out, int out_size) {
    const float *x = nullptr, *pos = nullptr, *W1 = nullptr, *b1 = nullptr,
                *W2 = nullptr, *b2 = nullptr;
    for (int i = 0; i < n_in; i++) {
        switch (in_sizes[i]) {
            case B_ * N_ * FIN_:  x   = (const float*)d_in[i]; break;
            case B_ * N_ * 3:     pos = (const float*)d_in[i]; break;
            case (FIN_ + 3) * H_: W1  = (const float*)d_in[i]; break;
            case H_:              b1  = (const float*)d_in[i]; break;
            case H_ * FOUT_:      W2  = (const float*)d_in[i]; break;
            case FOUT_:           b2  = (const float*)d_in[i]; break;
            default: break; // batch ids reconstructed analytically
        }
    }
    float* out = (float*)d_out;

    const int total3 = BS_ * FOUT_ + BS_ * 3 + BS_;
    const int tail = (out_size >= total3) ? 1 : 0;

    u_kernel<<<(B_ * N_) / 64, 256>>>(x, W1, b1);

    cudaFuncSetAttribute(pipe_kernel,
                         cudaFuncAttributeMaxDynamicSharedMemorySize, SMEM_BYTES);

    for (int p = 0; p <= NCHUNK; p++) {
        const int fs0 = p * CH;
        const int fs1 = fs0 + CH;
        const int ws0 = (p - 1) * CH;
        const int grid = (p == 0) ? B_ : (B_ + WBLK);
        pipe_kernel<<<grid, 256, SMEM_BYTES>>>(pos, W1, W2, b2, out, tail,
                                               fs0, fs1, ws0);
    }
}